// round 7
// baseline (speedup 1.0000x reference)
#include <cuda_runtime.h>
#include <math.h>

#define NB 32
#define CD 64
#define TPB 192
#define NPAIR (TPB / 2)        // 96 pairs
#define RPB (NPAIR * 4)        // 384 rows/block, 4 rows per thread (half-split)
#define ZSTRIDE 17             // float4s per row (16 data + 1 pad); 68 words ≡ 4 mod 32

// ---- packed fp32x2 helpers (Blackwell) ----
__device__ __forceinline__ void fma2(unsigned long long& d,
                                     unsigned long long a,
                                     unsigned long long b) {
    asm("fma.rn.f32x2 %0, %1, %2, %0;" : "+l"(d) : "l"(a), "l"(b));
}
__device__ __forceinline__ unsigned long long splat2(float x) {
    unsigned long long r;
    unsigned int u = __float_as_uint(x);
    asm("mov.b64 %0, {%1, %1};" : "=l"(r) : "r"(u));
    return r;
}
__device__ __forceinline__ void unpack2(unsigned long long v, float& lo, float& hi) {
    unsigned int a, b;
    asm("mov.b64 {%0, %1}, %2;" : "=r"(a), "=r"(b) : "l"(v));
    lo = __uint_as_float(a);
    hi = __uint_as_float(b);
}

__global__ void gc_init_util(const float* __restrict__ u_in,
                             float* __restrict__ u_out) {
    int i = threadIdx.x;
    if (i < NB) u_out[i] = u_in[i];
}

__global__ __launch_bounds__(TPB, 2)
void gc_main(const float* __restrict__ z,
             const float* __restrict__ protos,
             float* __restrict__ act,
             float* __restrict__ assign,
             float* __restrict__ util,
             int B) {
    __shared__ float4      s_z[RPB * ZSTRIDE];   // 104.4 KB padded full-64d tile
    __shared__ ulonglong2  s_pp[2 * CD * 4];     // 8 KB: [half][d][4] basin-pair quads
    __shared__ int         s_hist[NB];

    float4* s_res = s_z;                          // aliased: s_z dead after mainloop

    const int tid  = threadIdx.x;
    const int base = blockIdx.x * RPB;
    const int p    = tid >> 1;          // pair id 0..95
    const int half = tid & 1;           // 0: basins 0-15, 1: basins 16-31

    // ---- proto table: f2[h*512 + d*8 + j] = (proto[2*(8h+j)][d], proto[2*(8h+j)+1][d])
    {
        float2* f2 = (float2*)s_pp;
        for (int idx = tid; idx < 2 * CD * 8; idx += TPB) {
            int h = idx >> 9;
            int r = idx & 511;
            int d = r >> 3;
            int j = r & 7;
            int P = 8 * h + j;
            f2[idx] = make_float2(protos[(2 * P) * CD + d],
                                  protos[(2 * P + 1) * CD + d]);
        }
        if (tid < NB) s_hist[tid] = 0;
    }

    // ---- stage full 64-d z tile: coalesced LDG.128, padded STS (conflict-free)
    #pragma unroll
    for (int it = 0; it < (RPB * 16) / TPB; it++) {   // 32 iters
        int idx   = it * TPB + tid;
        int row_l = idx >> 4;
        int d4    = idx & 15;
        int grow  = base + row_l;
        if (grow < B) {
            float4 v = *(const float4*)(z + (size_t)grow * CD + d4 * 4);
            s_z[row_l * ZSTRIDE + d4] = v;
        }
    }
    __syncthreads();

    unsigned long long acc[4][8];
    #pragma unroll
    for (int t = 0; t < 4; t++)
        #pragma unroll
        for (int k = 0; k < 8; k++) acc[t][k] = 0ull;

    const ulonglong2* ppH = &s_pp[half * (CD * 4)];
    const float4* zr0 = &s_z[(p +         0) * ZSTRIDE];
    const float4* zr1 = &s_z[(p +     NPAIR) * ZSTRIDE];
    const float4* zr2 = &s_z[(p + 2 * NPAIR) * ZSTRIDE];
    const float4* zr3 = &s_z[(p + 3 * NPAIR) * ZSTRIDE];

    #pragma unroll 4
    for (int d4 = 0; d4 < 16; d4++) {
        const float4 a4  = zr0[d4];
        const float4 b4  = zr1[d4];
        const float4 c4  = zr2[d4];
        const float4 d4v = zr3[d4];
        const float ae[4] = {a4.x, a4.y, a4.z, a4.w};
        const float be[4] = {b4.x, b4.y, b4.z, b4.w};
        const float ce[4] = {c4.x, c4.y, c4.z, c4.w};
        const float de[4] = {d4v.x, d4v.y, d4v.z, d4v.w};
        #pragma unroll
        for (int e = 0; e < 4; e++) {
            const ulonglong2* pp = ppH + (d4 * 4 + e) * 4;
            const unsigned long long za = splat2(ae[e]);
            const unsigned long long zb = splat2(be[e]);
            const unsigned long long zc = splat2(ce[e]);
            const unsigned long long zd = splat2(de[e]);
            #pragma unroll
            for (int q = 0; q < 4; q++) {
                const ulonglong2 w = pp[q];   // 2 basin pairs serve 4 rows
                fma2(acc[0][2 * q],     za, w.x);
                fma2(acc[0][2 * q + 1], za, w.y);
                fma2(acc[1][2 * q],     zb, w.x);
                fma2(acc[1][2 * q + 1], zb, w.y);
                fma2(acc[2][2 * q],     zc, w.x);
                fma2(acc[2][2 * q + 1], zc, w.y);
                fma2(acc[3][2 * q],     zd, w.x);
                fma2(acc[3][2 * q + 1], zd, w.y);
            }
        }
    }
    __syncthreads();   // s_z reads done; safe to alias as s_res

    // ---- per-row: local top-3 over own 16 basins, shfl-merge with partner lane
    #pragma unroll
    for (int j = 0; j < 4; j++) {
        const int rl  = p + j * NPAIR;
        const bool ok = (base + rl) < B;

        float v[16];
        #pragma unroll
        for (int k = 0; k < 8; k++)
            unpack2(acc[j][k], v[2 * k], v[2 * k + 1]);

        float l0 = -2.0f, l1 = -2.0f, l2 = -2.0f;
        int   j0 = 0,     j1 = 0,     j2 = 0;
        #pragma unroll
        for (int n = 0; n < 16; n++) {
            const float x = v[n];
            if (x > l2) {
                if (x > l1) {
                    if (x > l0) { l2 = l1; j2 = j1; l1 = l0; j1 = j0; l0 = x; j0 = n; }
                    else        { l2 = l1; j2 = j1; l1 = x;  j1 = n; }
                } else          { l2 = x;  j2 = n; }
            }
        }
        const int g0 = j0 + (half << 4);
        const int g1 = j1 + (half << 4);
        const int g2 = j2 + (half << 4);

        const float q0 = __shfl_xor_sync(0xFFFFFFFFu, l0, 1);
        const float q1 = __shfl_xor_sync(0xFFFFFFFFu, l1, 1);
        const float q2 = __shfl_xor_sync(0xFFFFFFFFu, l2, 1);
        const int   qp = __shfl_xor_sync(0xFFFFFFFFu, g0 | (g1 << 8) | (g2 << 16), 1);

        // a = low-half candidates (ties prefer a, matching stable top_k)
        const float a0 = half ? q0 : l0, a1 = half ? q1 : l1, a2 = half ? q2 : l2;
        const float b0 = half ? l0 : q0, b1 = half ? l1 : q1, b2 = half ? l2 : q2;
        const int ia0 = half ? (qp & 255)        : g0;
        const int ia1 = half ? ((qp >> 8) & 255) : g1;
        const int ia2 = half ? ((qp >> 16) & 255): g2;
        const int ib0 = half ? g0 : (qp & 255);
        const int ib1 = half ? g1 : ((qp >> 8) & 255);
        const int ib2 = half ? g2 : ((qp >> 16) & 255);

        const bool s0 = (a0 >= b0);
        const float m0 = s0 ? a0 : b0;  const int mi0 = s0 ? ia0 : ib0;
        const float ha = s0 ? a1 : a0;  const int hai = s0 ? ia1 : ia0;
        const float hb = s0 ? b0 : b1;  const int hbi = s0 ? ib0 : ib1;
        const bool s1 = (ha >= hb);
        const float m1 = s1 ? ha : hb;  const int mi1 = s1 ? hai : hbi;
        const float ha2 = s1 ? (s0 ? a2 : a1) : ha;
        const int   hai2= s1 ? (s0 ? ia2: ia1): hai;
        const float hb2 = s1 ? hb : (s0 ? b1 : b2);
        const int   hbi2= s1 ? hbi: (s0 ? ib1: ib2);
        const bool s2 = (ha2 >= hb2);
        const float m2 = s2 ? ha2 : hb2; const int mi2 = s2 ? hai2 : hbi2;

        if (half == 0 && ok) {
            const float x1  = __expf((m1 - m0) * 0.2f);
            const float x2  = __expf((m2 - m0) * 0.2f);
            const float inv = 1.0f / (1.0f + x1 + x2);
            s_res[rl] = make_float4(inv, x1 * inv, x2 * inv,
                                    __int_as_float(mi0 | (mi1 << 8) | (mi2 << 16)));
            assign[base + rl] = (float)mi0;
            atomicAdd(&s_hist[mi0], 1);
        }
    }
    __syncthreads();

    // ---- coalesced act stores: one 128B STG per row
    {
        const int warp = tid >> 5;
        const int lane = tid & 31;
        #pragma unroll 4
        for (int r = 0; r < RPB / (TPB / 32); r++) {     // 64 rows per warp
            const int rl   = warp * (RPB / (TPB / 32)) + r;
            const int grow = base + rl;
            if (grow < B) {
                const float4 res = s_res[rl];
                const int pk = __float_as_int(res.w);
                const int i0 = pk & 255, i1 = (pk >> 8) & 255, i2 = (pk >> 16) & 255;
                float val = 0.0f;
                if (lane == i0) val = res.x;
                if (lane == i1) val = res.y;
                if (lane == i2) val = res.z;
                act[(size_t)grow * NB + lane] = val;
            }
        }
    }

    if (tid < NB) {
        const int cnt = s_hist[tid];
        if (cnt) atomicAdd(&util[tid], (float)cnt);
    }
}

extern "C" void kernel_launch(void* const* d_in, const int* in_sizes, int n_in,
                              void* d_out, int out_size) {
    const float* z      = (const float*)d_in[0];
    const float* protos = (const float*)d_in[1];
    const float* u_in   = (const float*)d_in[2];

    const int B = in_sizes[0] / CD;

    float* out    = (float*)d_out;
    float* act    = out;
    float* assign = out + (size_t)B * NB;
    float* util   = out + (size_t)B * (NB + 1);

    gc_init_util<<<1, 32>>>(u_in, util);

    const int grid = (B + RPB - 1) / RPB;
    gc_main<<<grid, TPB>>>(z, protos, act, assign, util, B);
}

// round 8
// speedup vs baseline: 1.0236x; 1.0236x over previous
#include <cuda_runtime.h>
#include <math.h>

#define NB 32
#define CD 64
#define TPB 256
#define RPB 256            // rows per block; 128 row-pairs; lane-duo (even,odd) per pair
#define NPAIRS 128
#define D2C 16             // dim-pairs per chunk (32 dims)
#define ZSTRIDE 17         // float4 stride per row-pair (16 data + 1 pad)

__device__ __forceinline__ void fma2(unsigned long long& d,
                                     unsigned long long a,
                                     unsigned long long b) {
    asm("fma.rn.f32x2 %0, %1, %2, %0;" : "+l"(d) : "l"(a), "l"(b));
}
__device__ __forceinline__ void unpack2(unsigned long long v, float& lo, float& hi) {
    unsigned int a, b;
    asm("mov.b64 {%0, %1}, %2;" : "=r"(a), "=r"(b) : "l"(v));
    lo = __uint_as_float(a);
    hi = __uint_as_float(b);
}

__global__ void gc_init_util(const float* __restrict__ u_in,
                             float* __restrict__ u_out) {
    int i = threadIdx.x;
    if (i < NB) u_out[i] = u_in[i];
}

__global__ __launch_bounds__(TPB, 3)
void gc_main(const float* __restrict__ z,
             const float* __restrict__ protos,
             float* __restrict__ act,
             float* __restrict__ assign,
             float* __restrict__ util,
             int B) {
    // z tile: (r0[d], r1[d], r0[d+1], r1[d+1]) per col; 128 pairs x 16 cols (34.8 KB)
    __shared__ float4      s_zp[NPAIRS * ZSTRIDE];
    // duplicated proto: [n 0..15][d2 0..31][half] = (p,p @dim 2*d2, p,p @dim 2*d2+1) (16 KB)
    __shared__ ulonglong2  s_pd[16 * 32 * 2];
    __shared__ float4      s_res[RPB];           // 4 KB
    __shared__ int         s_hist[NB];

    const int tid  = threadIdx.x;
    const int base = blockIdx.x * RPB;
    const int q    = tid >> 1;          // duo id 0..127 (row-pair index)
    const int half = tid & 1;           // 0: basins 0-15, 1: basins 16-31

    // ---- build duplicated proto table
    {
        float4* pd4 = (float4*)s_pd;
        #pragma unroll
        for (int it = 0; it < (16 * 32 * 2) / TPB; it++) {  // 4 iters
            int idx = it * TPB + tid;
            int h   = idx & 1;
            int d2  = (idx >> 1) & 31;
            int n   = idx >> 6;
            int gb  = n + 16 * h;
            float a = protos[gb * CD + 2 * d2];
            float b = protos[gb * CD + 2 * d2 + 1];
            pd4[idx] = make_float4(a, a, b, b);
        }
        if (tid < NB) s_hist[tid] = 0;
    }

    unsigned long long acc[16];
    #pragma unroll
    for (int n = 0; n < 16; n++) acc[n] = 0ull;

    for (int c = 0; c < 2; c++) {
        __syncthreads();
        // ---- stage chunk: coalesced LDG.128, shfl-transpose into row-pair layout
        #pragma unroll
        for (int it = 0; it < (RPB * 8) / TPB; it++) {   // 8 iters
            int idx = it * TPB + tid;
            int r   = idx >> 3;            // local row 0..255
            int k   = idx & 7;             // 4-dim chunk within 32-dim slab
            int grow = base + r;
            float4 v = make_float4(0.f, 0.f, 0.f, 0.f);
            if (grow < B)
                v = *(const float4*)(z + (size_t)grow * CD + c * 32 + 4 * k);
            // partner lane (row r^1) is lane^8 within the warp
            float4 pv;
            pv.x = __shfl_xor_sync(0xFFFFFFFFu, v.x, 8);
            pv.y = __shfl_xor_sync(0xFFFFFFFFu, v.y, 8);
            pv.z = __shfl_xor_sync(0xFFFFFFFFu, v.z, 8);
            pv.w = __shfl_xor_sync(0xFFFFFFFFu, v.w, 8);
            int p = r >> 1;
            if ((r & 1) == 0) {
                // this lane = row 2p, pv = row 2p+1 -> dims 4k,4k+1 (col 2k)
                s_zp[p * ZSTRIDE + 2 * k] = make_float4(v.x, pv.x, v.y, pv.y);
            } else {
                // this lane = row 2p+1, pv = row 2p -> dims 4k+2,4k+3 (col 2k+1)
                s_zp[p * ZSTRIDE + 2 * k + 1] = make_float4(pv.z, v.z, pv.w, v.w);
            }
        }
        __syncthreads();

        // ---- mainloop: no operand formatting, LDS feeds FMA2 directly
        const ulonglong2* zrow = (const ulonglong2*)&s_zp[q * ZSTRIDE];
        #pragma unroll 2
        for (int d2l = 0; d2l < D2C; d2l++) {
            const ulonglong2 zz = zrow[d2l];   // (z-pair @ d, z-pair @ d+1)
            const int d2g = c * D2C + d2l;
            const ulonglong2* pd = &s_pd[d2g * 2 + half];
            #pragma unroll
            for (int n = 0; n < 16; n++) {
                const ulonglong2 w = pd[n * 64];   // (dup p @ d, dup p @ d+1)
                fma2(acc[n], zz.x, w.x);           // ascending d preserved
                fma2(acc[n], zz.y, w.y);
            }
        }
    }

    // ---- epilogue: per row (2 per duo) top-3 over own 16 basins, shfl-merge
    #pragma unroll
    for (int j = 0; j < 2; j++) {
        const int rl  = 2 * q + j;
        const bool ok = (base + rl) < B;

        float v[16];
        #pragma unroll
        for (int n = 0; n < 16; n++) {
            float lo, hi;
            unpack2(acc[n], lo, hi);
            v[n] = j ? hi : lo;
        }

        float l0 = -2.0f, l1 = -2.0f, l2 = -2.0f;
        int   j0 = 0,     j1 = 0,     j2 = 0;
        #pragma unroll
        for (int n = 0; n < 16; n++) {
            const float x = v[n];
            if (x > l2) {
                if (x > l1) {
                    if (x > l0) { l2 = l1; j2 = j1; l1 = l0; j1 = j0; l0 = x; j0 = n; }
                    else        { l2 = l1; j2 = j1; l1 = x;  j1 = n; }
                } else          { l2 = x;  j2 = n; }
            }
        }
        const int g0 = j0 + (half << 4);
        const int g1 = j1 + (half << 4);
        const int g2 = j2 + (half << 4);

        const float q0 = __shfl_xor_sync(0xFFFFFFFFu, l0, 1);
        const float q1 = __shfl_xor_sync(0xFFFFFFFFu, l1, 1);
        const float q2 = __shfl_xor_sync(0xFFFFFFFFu, l2, 1);
        const int   qp = __shfl_xor_sync(0xFFFFFFFFu, g0 | (g1 << 8) | (g2 << 16), 1);

        // a = low-half candidates (ties prefer a, matching stable top_k)
        const float a0 = half ? q0 : l0, a1 = half ? q1 : l1, a2 = half ? q2 : l2;
        const float b0 = half ? l0 : q0, b1 = half ? l1 : q1, b2 = half ? l2 : q2;
        const int ia0 = half ? (qp & 255)        : g0;
        const int ia1 = half ? ((qp >> 8) & 255) : g1;
        const int ia2 = half ? ((qp >> 16) & 255): g2;
        const int ib0 = half ? g0 : (qp & 255);
        const int ib1 = half ? g1 : ((qp >> 8) & 255);
        const int ib2 = half ? g2 : ((qp >> 16) & 255);

        const bool s0 = (a0 >= b0);
        const float m0 = s0 ? a0 : b0;  const int mi0 = s0 ? ia0 : ib0;
        const float ha = s0 ? a1 : a0;  const int hai = s0 ? ia1 : ia0;
        const float hb = s0 ? b0 : b1;  const int hbi = s0 ? ib0 : ib1;
        const bool s1 = (ha >= hb);
        const float m1 = s1 ? ha : hb;  const int mi1 = s1 ? hai : hbi;
        const float ha2 = s1 ? (s0 ? a2 : a1) : ha;
        const int   hai2= s1 ? (s0 ? ia2: ia1): hai;
        const float hb2 = s1 ? hb : (s0 ? b1 : b2);
        const int   hbi2= s1 ? hbi: (s0 ? ib1: ib2);
        const bool s2 = (ha2 >= hb2);
        const float m2 = s2 ? ha2 : hb2; const int mi2 = s2 ? hai2 : hbi2;

        if (half == 0 && ok) {
            const float x1  = __expf((m1 - m0) * 0.2f);
            const float x2  = __expf((m2 - m0) * 0.2f);
            const float inv = 1.0f / (1.0f + x1 + x2);
            s_res[rl] = make_float4(inv, x1 * inv, x2 * inv,
                                    __int_as_float(mi0 | (mi1 << 8) | (mi2 << 16)));
            atomicAdd(&s_hist[mi0], 1);
        }
    }
    __syncthreads();

    // ---- coalesced act stores: one 128B STG per row
    {
        const int warp = tid >> 5;
        const int lane = tid & 31;
        #pragma unroll 4
        for (int r = 0; r < RPB / (TPB / 32); r++) {     // 32 rows per warp
            const int rl   = warp * (RPB / (TPB / 32)) + r;
            const int grow = base + rl;
            if (grow < B) {
                const float4 res = s_res[rl];
                const int pk = __float_as_int(res.w);
                const int i0 = pk & 255, i1 = (pk >> 8) & 255, i2 = (pk >> 16) & 255;
                float val = 0.0f;
                if (lane == i0) val = res.x;
                if (lane == i1) val = res.y;
                if (lane == i2) val = res.z;
                act[(size_t)grow * NB + lane] = val;
            }
        }
    }

    // ---- coalesced assignments (one row per thread; RPB == TPB)
    {
        const int grow = base + tid;
        if (grow < B)
            assign[grow] = (float)(__float_as_int(s_res[tid].w) & 255);
    }

    if (tid < NB) {
        const int cnt = s_hist[tid];
        if (cnt) atomicAdd(&util[tid], (float)cnt);
    }
}

extern "C" void kernel_launch(void* const* d_in, const int* in_sizes, int n_in,
                              void* d_out, int out_size) {
    const float* z      = (const float*)d_in[0];
    const float* protos = (const float*)d_in[1];
    const float* u_in   = (const float*)d_in[2];

    const int B = in_sizes[0] / CD;

    float* out    = (float*)d_out;
    float* act    = out;
    float* assign = out + (size_t)B * NB;
    float* util   = out + (size_t)B * (NB + 1);

    gc_init_util<<<1, 32>>>(u_in, util);

    const int grid = (B + RPB - 1) / RPB;
    gc_main<<<grid, TPB>>>(z, protos, act, assign, util, B);
}

// round 11
// speedup vs baseline: 1.2299x; 1.2016x over previous
#include <cuda_runtime.h>
#include <cstdint>

#define NB 32
#define CD 64
#define TPB 256
#define ROWS 256

// dynamic smem offsets (bytes)
#define SM_Z     0                  // 256 x 68 f32 = 69632 (aliased as sims 256x36 later)
#define SM_BH    69632              // 64 x 40 u32 = 10240
#define SM_BM    79872              // 64 x 40 u32 = 10240
#define SM_RES   90112              // 256 x float4 = 4096
#define SM_HIST  94208              // 32 ints
#define SM_TOTAL 94336

#define ZSTR 68                     // f32 stride of z tile (conflict-free frag loads)
#define BSTR 40                     // u32 stride of proto tables
#define SSTR 36                     // f32 stride of sims tile (16B-aligned rows)

__device__ __forceinline__ uint32_t f2tf(float x) {
    uint32_t r;
    asm("cvt.rna.tf32.f32 %0, %1;" : "=r"(r) : "f"(x));
    return r;
}
__device__ __forceinline__ void mma_tf32(float* c,
                                         uint32_t a0, uint32_t a1, uint32_t a2, uint32_t a3,
                                         uint32_t b0, uint32_t b1) {
    asm volatile(
        "mma.sync.aligned.m16n8k8.row.col.f32.tf32.tf32.f32 "
        "{%0,%1,%2,%3}, {%4,%5,%6,%7}, {%8,%9}, {%0,%1,%2,%3};"
        : "+f"(c[0]), "+f"(c[1]), "+f"(c[2]), "+f"(c[3])
        : "r"(a0), "r"(a1), "r"(a2), "r"(a3), "r"(b0), "r"(b1));
}

__global__ void gc_init_util(const float* __restrict__ u_in,
                             float* __restrict__ u_out) {
    int i = threadIdx.x;
    if (i < NB) u_out[i] = u_in[i];
}

__global__ __launch_bounds__(TPB, 2)
void gc_main(const float* __restrict__ z,
             const float* __restrict__ protos,
             float* __restrict__ act,
             float* __restrict__ assign,
             float* __restrict__ util,
             int B) {
    extern __shared__ char smem[];
    float*    s_z    = (float*)(smem + SM_Z);
    uint32_t* s_bh   = (uint32_t*)(smem + SM_BH);
    uint32_t* s_bm   = (uint32_t*)(smem + SM_BM);
    float*    s_sims = (float*)(smem + SM_Z);      // alias, used after sync
    float4*   s_res  = (float4*)(smem + SM_RES);
    int*      s_hist = (int*)(smem + SM_HIST);

    const int tid  = threadIdx.x;
    const int base = blockIdx.x * ROWS;
    const int w    = tid >> 5;
    const int lane = tid & 31;
    const int g    = lane >> 2;      // groupID
    const int c    = lane & 3;       // thread-in-group

    // ---- stage protos as tf32 h/m in [k][n] layout
    #pragma unroll
    for (int it = 0; it < (CD * NB) / TPB; it++) {   // 8 iters
        int idx = it * TPB + tid;
        int k = idx >> 5;
        int n = idx & 31;
        float v = protos[n * CD + k];
        uint32_t h = f2tf(v);
        uint32_t m = f2tf(v - __uint_as_float(h));
        s_bh[k * BSTR + n] = h;
        s_bm[k * BSTR + n] = m;
    }
    if (tid < NB) s_hist[tid] = 0;

    // ---- stage z fp32 tile: coalesced LDG.128, padded STS (zero-fill OOB)
    #pragma unroll
    for (int it = 0; it < (ROWS * 16) / TPB; it++) {  // 16 iters
        int idx = it * TPB + tid;
        int row = idx >> 4;
        int d4  = idx & 15;
        int grow = base + row;
        float4 v = make_float4(0.f, 0.f, 0.f, 0.f);
        if (grow < B) v = *(const float4*)(z + (size_t)grow * CD + d4 * 4);
        *(float4*)&s_z[row * ZSTR + d4 * 4] = v;
    }
    __syncthreads();

    // ---- mainloop: warp owns rows [w*32, w*32+32); 2 m16 tiles x 4 n-tiles
    float acc[2][4][4];
    #pragma unroll
    for (int t = 0; t < 2; t++)
        #pragma unroll
        for (int nt = 0; nt < 4; nt++)
            #pragma unroll
            for (int j = 0; j < 4; j++) acc[t][nt][j] = 0.0f;

    const int rb = w * 32;

    #pragma unroll 2
    for (int k = 0; k < 8; k++) {
        const int kr = 8 * k + c;
        // B fragments (h and m) for 4 n-tiles
        uint32_t bh0[4], bh1[4], bm0[4], bm1[4];
        #pragma unroll
        for (int nt = 0; nt < 4; nt++) {
            const int n = nt * 8 + g;
            bh0[nt] = s_bh[kr * BSTR + n];
            bh1[nt] = s_bh[(kr + 4) * BSTR + n];
            bm0[nt] = s_bm[kr * BSTR + n];
            bm1[nt] = s_bm[(kr + 4) * BSTR + n];
        }
        #pragma unroll
        for (int t = 0; t < 2; t++) {
            const int r = rb + t * 16 + g;
            const float x0 = s_z[r * ZSTR + kr];
            const float x1 = s_z[(r + 8) * ZSTR + kr];
            const float x2 = s_z[r * ZSTR + kr + 4];
            const float x3 = s_z[(r + 8) * ZSTR + kr + 4];
            const uint32_t ah0 = f2tf(x0), ah1 = f2tf(x1);
            const uint32_t ah2 = f2tf(x2), ah3 = f2tf(x3);
            const uint32_t am0 = f2tf(x0 - __uint_as_float(ah0));
            const uint32_t am1 = f2tf(x1 - __uint_as_float(ah1));
            const uint32_t am2 = f2tf(x2 - __uint_as_float(ah2));
            const uint32_t am3 = f2tf(x3 - __uint_as_float(ah3));
            #pragma unroll
            for (int nt = 0; nt < 4; nt++) {
                mma_tf32(acc[t][nt], ah0, ah1, ah2, ah3, bh0[nt], bh1[nt]);  // hh
                mma_tf32(acc[t][nt], ah0, ah1, ah2, ah3, bm0[nt], bm1[nt]);  // hm
                mma_tf32(acc[t][nt], am0, am1, am2, am3, bh0[nt], bh1[nt]);  // mh
            }
        }
    }
    __syncthreads();   // all z reads done; alias region as sims

    // ---- scatter C fragments to sims tile [row][32] (stride 36)
    #pragma unroll
    for (int t = 0; t < 2; t++) {
        const int r = rb + t * 16 + g;
        #pragma unroll
        for (int nt = 0; nt < 4; nt++) {
            const int col = nt * 8 + 2 * c;
            *(float2*)&s_sims[r * SSTR + col]       = make_float2(acc[t][nt][0], acc[t][nt][1]);
            *(float2*)&s_sims[(r + 8) * SSTR + col] = make_float2(acc[t][nt][2], acc[t][nt][3]);
        }
    }
    __syncthreads();

    // ---- per-thread row epilogue: top-3 + softmax (exact, stable ties)
    {
        const int grow = base + tid;
        float v[32];
        #pragma unroll
        for (int j = 0; j < 8; j++) {
            float4 q = *(float4*)&s_sims[tid * SSTR + 4 * j];
            v[4 * j] = q.x; v[4 * j + 1] = q.y; v[4 * j + 2] = q.z; v[4 * j + 3] = q.w;
        }
        float v0 = -2.0f, v1 = -2.0f, v2 = -2.0f;
        int   i0 = 0,     i1 = 0,     i2 = 0;
        #pragma unroll
        for (int n = 0; n < NB; n++) {
            const float x = v[n];
            if (x > v2) {
                if (x > v1) {
                    if (x > v0) { v2 = v1; i2 = i1; v1 = v0; i1 = i0; v0 = x; i0 = n; }
                    else        { v2 = v1; i2 = i1; v1 = x;  i1 = n; }
                } else          { v2 = x;  i2 = n; }
            }
        }
        if (grow < B) {
            const float e1  = __expf((v1 - v0) * 0.2f);
            const float e2  = __expf((v2 - v0) * 0.2f);
            const float inv = 1.0f / (1.0f + e1 + e2);
            s_res[tid] = make_float4(inv, e1 * inv, e2 * inv,
                                     __int_as_float(i0 | (i1 << 8) | (i2 << 16)));
            assign[grow] = (float)i0;
            atomicAdd(&s_hist[i0], 1);
        }
    }
    __syncthreads();

    // ---- coalesced act stores: one 128B STG per row
    #pragma unroll 4
    for (int r = 0; r < 32; r++) {
        const int rl   = w * 32 + r;
        const int grow = base + rl;
        if (grow < B) {
            const float4 res = s_res[rl];
            const int pk = __float_as_int(res.w);
            const int i0 = pk & 255, i1 = (pk >> 8) & 255, i2 = (pk >> 16) & 255;
            float val = 0.0f;
            if (lane == i0) val = res.x;
            if (lane == i1) val = res.y;
            if (lane == i2) val = res.z;
            act[(size_t)grow * NB + lane] = val;
        }
    }

    if (tid < NB) {
        const int cnt = s_hist[tid];
        if (cnt) atomicAdd(&util[tid], (float)cnt);
    }
}

extern "C" void kernel_launch(void* const* d_in, const int* in_sizes, int n_in,
                              void* d_out, int out_size) {
    const float* z      = (const float*)d_in[0];
    const float* protos = (const float*)d_in[1];
    const float* u_in   = (const float*)d_in[2];

    const int B = in_sizes[0] / CD;

    float* out    = (float*)d_out;
    float* act    = out;
    float* assign = out + (size_t)B * NB;
    float* util   = out + (size_t)B * (NB + 1);

    cudaFuncSetAttribute(gc_main, cudaFuncAttributeMaxDynamicSharedMemorySize, SM_TOTAL);

    gc_init_util<<<1, 32>>>(u_in, util);

    const int grid = (B + ROWS - 1) / ROWS;
    gc_main<<<grid, TPB, SM_TOTAL>>>(z, protos, act, assign, util, B);
}